// round 4
// baseline (speedup 1.0000x reference)
#include <cuda_runtime.h>
#include <cstdint>

#define NTOK 8192
#define HD   1024
#define NE   8

#define KC      32            // k elements per smem stage
#define NSTAGES (HD / KC)     // 32
#define S_WORDS 40            // smem row stride in floats (128B data + 32B pad)

// double-buffer offsets in floats (A: 128 rows, B: 128 rows, stride 40)
#define FA_OFF(b) ((b) * 10240)
#define FB_OFF(b) (5120 + (b) * 10240)
#define F_TOK 20480

// ---------------- device scratch (static, no allocs) ----------------
__device__ int   g_count[NE];
__device__ int   g_tok[NE][NTOK];      // token id
__device__ float g_gwt[NE][NTOK];      // gate weight
__device__ __align__(16) float g_xt[NTOK * HD];     // tf32-rounded x
__device__ __align__(16) float g_wt[NE * HD * HD];  // [e][o][h], tf32-rounded (transposed)

// ---------------- helpers ----------------
__device__ __forceinline__ uint32_t smem_u32(const void* p) {
    uint32_t a;
    asm("{ .reg .u64 t; cvta.to.shared.u64 t, %1; cvt.u32.u64 %0, t; }" : "=r"(a) : "l"(p));
    return a;
}
__device__ __forceinline__ float rna_tf32(float x) {
    uint32_t u;
    asm("cvt.rna.tf32.f32 %0, %1;" : "=r"(u) : "f"(x));
    return __uint_as_float(u);
}
#define CP_ASYNC16(dst, src) \
    asm volatile("cp.async.cg.shared.global [%0], [%1], 16;" :: "r"(dst), "l"(src) : "memory")
#define CP_COMMIT() asm volatile("cp.async.commit_group;" ::: "memory")
#define CP_WAIT1()  asm volatile("cp.async.wait_group 1;" ::: "memory")
#define CP_WAIT0()  asm volatile("cp.async.wait_group 0;" ::: "memory")

__device__ __forceinline__ void mma_tf32(float& d0, float& d1, float& d2, float& d3,
                                         uint32_t a0, uint32_t a1, uint32_t a2, uint32_t a3,
                                         uint32_t b0, uint32_t b1) {
    asm volatile(
        "mma.sync.aligned.m16n8k8.row.col.f32.tf32.tf32.f32 "
        "{%0,%1,%2,%3}, {%4,%5,%6,%7}, {%8,%9}, {%0,%1,%2,%3};"
        : "+f"(d0), "+f"(d1), "+f"(d2), "+f"(d3)
        : "r"(a0), "r"(a1), "r"(a2), "r"(a3), "r"(b0), "r"(b1));
}

// ---------------- kernel 1: zero counters + zero output ----------------
__global__ void __launch_bounds__(256) zero_kernel(float* __restrict__ out) {
    if (blockIdx.x == 0 && threadIdx.x < NE) g_count[threadIdx.x] = 0;
    int i = (blockIdx.x * 256 + threadIdx.x) * 4;
    if (i < NTOK * HD) *(float4*)(out + i) = make_float4(0.f, 0.f, 0.f, 0.f);
}

// ---------------- kernel 2: gate + routing + x tf32 round ----------------
__global__ void __launch_bounds__(256) gate_kernel(const float* __restrict__ x,
                                                   const float* __restrict__ gw) {
    int warp = threadIdx.x >> 5, lane = threadIdx.x & 31;
    int t = blockIdx.x * 8 + warp;
    const float* xr = x + (size_t)t * HD;
    float a[8];
#pragma unroll
    for (int e = 0; e < 8; e++) a[e] = 0.f;
    const float4* gw4 = (const float4*)gw;
    for (int j = lane; j < HD; j += 32) {
        float xv = xr[j];
        g_xt[(size_t)t * HD + j] = rna_tf32(xv);
        float4 p = gw4[j * 2], q = gw4[j * 2 + 1];
        a[0] += xv * p.x; a[1] += xv * p.y; a[2] += xv * p.z; a[3] += xv * p.w;
        a[4] += xv * q.x; a[5] += xv * q.y; a[6] += xv * q.z; a[7] += xv * q.w;
    }
#pragma unroll
    for (int e = 0; e < 8; e++)
#pragma unroll
        for (int off = 16; off; off >>= 1)
            a[e] += __shfl_xor_sync(0xffffffffu, a[e], off);
    if (lane == 0) {
        float v0 = -1e30f, v1 = -1e30f; int i0 = 0, i1 = 0;
#pragma unroll
        for (int e = 0; e < 8; e++) {
            float v = a[e];
            if (v > v0) { v1 = v0; i1 = i0; v0 = v; i0 = e; }
            else if (v > v1) { v1 = v; i1 = e; }
        }
        float e1 = expf(v1 - v0);
        float inv = 1.0f / (1.0f + e1);
        int p0 = atomicAdd(&g_count[i0], 1);
        g_tok[i0][p0] = t; g_gwt[i0][p0] = inv;
        int p1 = atomicAdd(&g_count[i1], 1);
        g_tok[i1][p1] = t; g_gwt[i1][p1] = e1 * inv;
    }
}

// ---------------- kernel 3: transpose + tf32-round expert weights ----------------
// g_wt[e][o][h] = tf32(expert_w[e][h][o])   (k=h contiguous for B tiles)
__global__ void __launch_bounds__(256) wtrans_kernel(const float* __restrict__ w) {
    __shared__ float tile[32][33];
    int e = blockIdx.z;
    int ob = blockIdx.x * 32, hb = blockIdx.y * 32;
    int tx = threadIdx.x, ty = threadIdx.y;   // 32 x 8
    const float* we = w + (size_t)e * HD * HD;
#pragma unroll
    for (int i = 0; i < 4; i++) {
        int h = hb + ty + i * 8;
        tile[ty + i * 8][tx] = we[(size_t)h * HD + ob + tx];
    }
    __syncthreads();
    float* wo = g_wt + (size_t)e * HD * HD;
#pragma unroll
    for (int i = 0; i < 4; i++) {
        int o = ob + ty + i * 8;
        wo[(size_t)o * HD + hb + tx] = rna_tf32(tile[tx][ty + i * 8]);
    }
}

// ---------------- kernel 4: gathered expert GEMM (mma.sync tf32) ----------------
static constexpr uint32_t GEMM_SMEM_BYTES = (20480 + 256) * 4;  // 82944

__device__ __forceinline__ void load_stage(uint32_t sbase, const int* tok,
                                           const float* wbase, int tid,
                                           int s, int b) {
    int k0 = s * KC;
    int fa = FA_OFF(b), fb = FB_OFF(b);
    // A tile: 128 rows x 32 floats (gathered by token)
#pragma unroll
    for (int i = 0; i < 4; i++) {
        int q = tid + i * 256;
        int r = q >> 3, seg = q & 7;
        const float* src = g_xt + (size_t)tok[r] * HD + k0 + seg * 4;
        uint32_t dst = sbase + (uint32_t)(fa + r * S_WORDS) * 4u + seg * 16u;
        CP_ASYNC16(dst, src);
    }
    // B tile: 128 n-rows x 32 floats (contiguous k in g_wt)
#pragma unroll
    for (int i = 0; i < 4; i++) {
        int q = tid + i * 256;
        int r = q >> 3, seg = q & 7;
        const float* src = wbase + (size_t)r * HD + k0 + seg * 4;
        uint32_t dst = sbase + (uint32_t)(fb + r * S_WORDS) * 4u + seg * 16u;
        CP_ASYNC16(dst, src);
    }
    CP_COMMIT();
}

__global__ void __launch_bounds__(256, 2) moe_gemm_kernel(float* __restrict__ out) {
    int e = blockIdx.z, nt128 = blockIdx.y, mt128 = blockIdx.x;
    int cnt = g_count[e];
    int m0 = mt128 * 128;
    if (m0 >= cnt) return;
    int n0 = nt128 * 128;

    extern __shared__ float smemf[];
    uint32_t sbase = smem_u32(smemf);
    int* tok = (int*)(smemf + F_TOK);
    float* twt = smemf + F_TOK + 128;

    int tid = threadIdx.x, wid = tid >> 5, lane = tid & 31;
    int wm = wid >> 2, wn = wid & 3;          // warp grid 2 x 4
    int g = lane >> 2, tg = lane & 3;

    if (tid < 128) {
        int idx = m0 + tid;
        int p = 0; float wv = 0.f;
        if (idx < cnt) { p = g_tok[e][idx]; wv = g_gwt[e][idx]; }
        tok[tid] = p; twt[tid] = wv;
    }
    __syncthreads();

    const float* wbase = g_wt + ((size_t)e * HD + (size_t)n0) * HD;

    float d[4][4][4];
#pragma unroll
    for (int mt = 0; mt < 4; mt++)
#pragma unroll
        for (int nt = 0; nt < 4; nt++)
#pragma unroll
            for (int r = 0; r < 4; r++) d[mt][nt][r] = 0.f;

    load_stage(sbase, tok, wbase, tid, 0, 0);
    load_stage(sbase, tok, wbase, tid, 1, 1);

    // per-thread fragment base offsets (in words)
    int a_off = (wm * 64 + g) * S_WORDS + 2 * tg;   // + mt*16*S + kb*8 ; +8*S for hi rows
    int b_off = (wn * 32 + g) * S_WORDS + 2 * tg;   // + nt*8*S  + kb*8

    for (int s = 0; s < NSTAGES; s++) {
        int b = s & 1;
        if (s + 2 < NSTAGES) { CP_WAIT1(); } else { CP_WAIT0(); }
        __syncthreads();

        const uint32_t* As = (const uint32_t*)(smemf + FA_OFF(b));
        const uint32_t* Bs = (const uint32_t*)(smemf + FB_OFF(b));
#pragma unroll
        for (int kb = 0; kb < 4; kb++) {
            uint2 afr[4][2];
#pragma unroll
            for (int mt = 0; mt < 4; mt++) {
                int base = a_off + mt * 16 * S_WORDS + kb * 8;
                afr[mt][0] = *(const uint2*)(As + base);                 // a0, a2
                afr[mt][1] = *(const uint2*)(As + base + 8 * S_WORDS);   // a1, a3
            }
            uint2 bfr[4];
#pragma unroll
            for (int nt = 0; nt < 4; nt++)
                bfr[nt] = *(const uint2*)(Bs + b_off + nt * 8 * S_WORDS + kb * 8);
#pragma unroll
            for (int mt = 0; mt < 4; mt++)
#pragma unroll
                for (int nt = 0; nt < 4; nt++)
                    mma_tf32(d[mt][nt][0], d[mt][nt][1], d[mt][nt][2], d[mt][nt][3],
                             afr[mt][0].x, afr[mt][1].x, afr[mt][0].y, afr[mt][1].y,
                             bfr[nt].x, bfr[nt].y);
        }
        __syncthreads();
        if (s + 2 < NSTAGES)
            load_stage(sbase, tok, wbase, tid, s + 2, b);
    }

    // Epilogue: weight-scale and atomic-accumulate into out (REDG, no-return)
#pragma unroll
    for (int mt = 0; mt < 4; mt++) {
        int r0 = wm * 64 + mt * 16 + g;
        int r1 = r0 + 8;
        int t0 = tok[r0], t1 = tok[r1];
        float w0 = twt[r0], w1 = twt[r1];
        float* o0 = out + (size_t)t0 * HD + n0 + wn * 32 + tg * 2;
        float* o1 = out + (size_t)t1 * HD + n0 + wn * 32 + tg * 2;
#pragma unroll
        for (int nt = 0; nt < 4; nt++) {
            atomicAdd(o0 + nt * 8,     d[mt][nt][0] * w0);
            atomicAdd(o0 + nt * 8 + 1, d[mt][nt][1] * w0);
            atomicAdd(o1 + nt * 8,     d[mt][nt][2] * w1);
            atomicAdd(o1 + nt * 8 + 1, d[mt][nt][3] * w1);
        }
    }
}

// ---------------- launch ----------------
extern "C" void kernel_launch(void* const* d_in, const int* in_sizes, int n_in,
                              void* d_out, int out_size) {
    const float* x  = (const float*)d_in[0];
    const float* gw = (const float*)d_in[1];
    const float* ew = (const float*)d_in[2];
    float* out = (float*)d_out;

    cudaFuncSetAttribute(moe_gemm_kernel,
                         cudaFuncAttributeMaxDynamicSharedMemorySize, GEMM_SMEM_BYTES);

    zero_kernel<<<NTOK * HD / 1024, 256>>>(out);
    gate_kernel<<<NTOK / 8, 256>>>(x, gw);
    wtrans_kernel<<<dim3(32, 32, 8), dim3(32, 8)>>>(ew);
    moe_gemm_kernel<<<dim3(64, 8, 8), 256, GEMM_SMEM_BYTES>>>(out);
}